// round 16
// baseline (speedup 1.0000x reference)
#include <cuda_runtime.h>
#include <cuda_bf16.h>
#include <cstdint>

#define BATCH 4
#define NPTS  4096
#define DIM   64
#define LOG2E 1.4426950408889634f
#define SC_F  24.0224478f          // sqrt(log2e)/0.05
#define TWOL  2.8853900817779268f  // 2*log2e

#define BM 64
#define BN 64
#define NJT (NPTS/BN)   // 64
#define NIT (NPTS/BM)   // 64
#define NCHUNK 8
#define TPC (NJT/NCHUNK)            // 8 j-tiles per work item

#define ROWB 272                    // 256B packed row + 16B pad
#define OFF_A 0
#define SZ_A  (64*ROWB)             // 17408
#define OFF_B (SZ_A)                // 17408
#define SZ_B  (64*ROWB)             // 17408
#define OFF_P (OFF_B + 2*SZ_B)      // 52224
#define SZ_P  1280                  // [0,1024) float4 xj ; [1024,1280) -cn2
#define OFF_M (OFF_P + 4*SZ_P)      // 57344 ; 64 rows x 5 floats
#define SMEM_TOTAL (OFF_M + 64*5*4) // 58624

// scratch (no allocation allowed)
__device__ __align__(16) uint32_t g_pk1[BATCH*NPTS*64]; // [hi64|lo64] bf16, f1*2log2e
__device__ __align__(16) uint32_t g_pk2[BATCH*NPTS*64]; // [hi64|lo64] bf16, f2 raw
__device__ __align__(16) float4   g_pi[BATCH*NPTS];     // xi*SC
__device__ __align__(16) float4   g_pj[BATCH*NPTS];     // xj*SC, w = -|xj|^2
__device__ __align__(16) float    g_cn2[BATCH*NPTS];    // NEGATED log2e*|f2|^2
__device__ __align__(16) float    g_stats[BATCH*NIT*NCHUNK*5*64]; // per-item [5][64]
__device__ float g_partial[BATCH*NIT];

__device__ __forceinline__ float ex2(float x){
    float y; asm("ex2.approx.ftz.f32 %0, %1;" : "=f"(y) : "f"(x)); return y;
}
__device__ __forceinline__ void cpa16(uint32_t dst, const void* src){
    asm volatile("cp.async.cg.shared.global [%0], [%1], 16;\n" :: "r"(dst), "l"(src));
}
__device__ __forceinline__ void ldmx4(uint32_t& r0,uint32_t& r1,uint32_t& r2,uint32_t& r3, uint32_t a){
    asm volatile("ldmatrix.sync.aligned.m8n8.x4.shared.b16 {%0,%1,%2,%3}, [%4];\n"
                 : "=r"(r0),"=r"(r1),"=r"(r2),"=r"(r3) : "r"(a));
}
__device__ __forceinline__ void mma16816(float* c, const uint32_t* a, uint32_t b0, uint32_t b1){
    asm volatile("mma.sync.aligned.m16n8k16.row.col.f32.bf16.bf16.f32 "
                 "{%0,%1,%2,%3}, {%4,%5,%6,%7}, {%8,%9}, {%0,%1,%2,%3};\n"
                 : "+f"(c[0]),"+f"(c[1]),"+f"(c[2]),"+f"(c[3])
                 : "r"(a[0]),"r"(a[1]),"r"(a[2]),"r"(a[3]), "r"(b0),"r"(b1));
}
// ---- packed f32x2 helpers ----
__device__ __forceinline__ uint64_t pk2(float lo, float hi){
    uint64_t r; asm("mov.b64 %0, {%1, %2};" : "=l"(r) : "f"(lo), "f"(hi)); return r;
}
__device__ __forceinline__ void upk2(uint64_t v, float& lo, float& hi){
    asm("mov.b64 {%0, %1}, %2;" : "=f"(lo), "=f"(hi) : "l"(v));
}
__device__ __forceinline__ uint64_t fma2(uint64_t a, uint64_t b, uint64_t c){
    uint64_t r; asm("fma.rn.f32x2 %0, %1, %2, %3;" : "=l"(r) : "l"(a), "l"(b), "l"(c)); return r;
}
__device__ __forceinline__ uint64_t add2(uint64_t a, uint64_t b){
    uint64_t r; asm("add.rn.f32x2 %0, %1, %2;" : "=l"(r) : "l"(a), "l"(b)); return r;
}
__device__ __forceinline__ uint32_t bfp(float a, float b){
    __nv_bfloat16 ha = __float2bfloat16(a), hb = __float2bfloat16(b);
    return (uint32_t)__bfloat16_as_ushort(ha) | ((uint32_t)__bfloat16_as_ushort(hb)<<16);
}

// ---------------------------------------------------------------------------
// prep: one thread per row. Identical byte layout to the warp-per-row version.
// ---------------------------------------------------------------------------
__global__ void prep_kernel(const float* __restrict__ pts,
                            const float* __restrict__ f1,
                            const float* __restrict__ f2)
{
    int r = blockIdx.x*blockDim.x + threadIdx.x;
    if (r >= BATCH*NPTS) return;
    const float4* r1 = (const float4*)(f1 + (size_t)r*DIM);
    const float4* r2 = (const float4*)(f2 + (size_t)r*DIM);
    uint4* o1 = (uint4*)((char*)g_pk1 + (size_t)r*256);
    uint4* o2 = (uint4*)((char*)g_pk2 + (size_t)r*256);

    float n2 = 0.0f;
    #pragma unroll
    for(int c=0;c<4;c++){
        uint32_t hi1[8], lo1[8], hi2[8], lo2[8];
        #pragma unroll
        for(int k=0;k<4;k++){
            float4 q = r1[c*4+k];
            float s0=q.x*TWOL, s1=q.y*TWOL, s2=q.z*TWOL, s3=q.w*TWOL;
            __nv_bfloat16 h0=__float2bfloat16(s0), h1=__float2bfloat16(s1);
            __nv_bfloat16 h2=__float2bfloat16(s2), h3=__float2bfloat16(s3);
            hi1[k*2+0] = (uint32_t)__bfloat16_as_ushort(h0) | ((uint32_t)__bfloat16_as_ushort(h1)<<16);
            hi1[k*2+1] = (uint32_t)__bfloat16_as_ushort(h2) | ((uint32_t)__bfloat16_as_ushort(h3)<<16);
            lo1[k*2+0] = bfp(s0-__bfloat162float(h0), s1-__bfloat162float(h1));
            lo1[k*2+1] = bfp(s2-__bfloat162float(h2), s3-__bfloat162float(h3));

            float4 p = r2[c*4+k];
            n2 = fmaf(p.x,p.x, fmaf(p.y,p.y, fmaf(p.z,p.z, fmaf(p.w,p.w, n2))));
            __nv_bfloat16 H0=__float2bfloat16(p.x), H1=__float2bfloat16(p.y);
            __nv_bfloat16 H2=__float2bfloat16(p.z), H3=__float2bfloat16(p.w);
            hi2[k*2+0] = (uint32_t)__bfloat16_as_ushort(H0) | ((uint32_t)__bfloat16_as_ushort(H1)<<16);
            hi2[k*2+1] = (uint32_t)__bfloat16_as_ushort(H2) | ((uint32_t)__bfloat16_as_ushort(H3)<<16);
            lo2[k*2+0] = bfp(p.x-__bfloat162float(H0), p.y-__bfloat162float(H1));
            lo2[k*2+1] = bfp(p.z-__bfloat162float(H2), p.w-__bfloat162float(H3));
        }
        o1[c*2+0] = make_uint4(hi1[0],hi1[1],hi1[2],hi1[3]);
        o1[c*2+1] = make_uint4(hi1[4],hi1[5],hi1[6],hi1[7]);
        o1[8+c*2+0] = make_uint4(lo1[0],lo1[1],lo1[2],lo1[3]);
        o1[8+c*2+1] = make_uint4(lo1[4],lo1[5],lo1[6],lo1[7]);
        o2[c*2+0] = make_uint4(hi2[0],hi2[1],hi2[2],hi2[3]);
        o2[c*2+1] = make_uint4(hi2[4],hi2[5],hi2[6],hi2[7]);
        o2[8+c*2+0] = make_uint4(lo2[0],lo2[1],lo2[2],lo2[3]);
        o2[8+c*2+1] = make_uint4(lo2[4],lo2[5],lo2[6],lo2[7]);
    }
    float px = pts[(size_t)r*3+0]*SC_F;
    float py = pts[(size_t)r*3+1]*SC_F;
    float pz = pts[(size_t)r*3+2]*SC_F;
    g_pi[r]  = make_float4(px,py,pz,0.0f);
    g_pj[r]  = make_float4(px,py,pz, -fmaf(px,px, fmaf(py,py, pz*pz)));
    g_cn2[r] = -(n2*LOG2E);
}

// ---------------------------------------------------------------------------
__device__ __forceinline__ void load_B_tile(uint32_t sb, int tid, int b, int jt){
    const char* gB = (const char*)(g_pk2 + (size_t)(b*NPTS + jt*BN)*64);
    const uint32_t dst = sb + OFF_B + (jt&1)*SZ_B;
    #pragma unroll
    for(int q=0;q<4;q++){
        int idx=q*256+tid, r=idx>>4, c=idx&15;
        cpa16(dst + r*ROWB + c*16, gB + r*256 + c*16);
    }
    const uint32_t pdst = sb + OFF_P + (jt&3)*SZ_P;
    const int j0 = jt*BN;
    if (tid<64) cpa16(pdst + tid*16, (const char*)(g_pj + b*NPTS + j0 + tid));
    else if (tid<80) cpa16(pdst + 1024 + (tid-64)*16,
                           (const char*)(g_cn2 + b*NPTS + j0 + (tid-64)*4));
}

// ---------------------------------------------------------------------------
// Work item = (b, i-tile, j-chunk of 8 tiles). 2048 items for load balance.
// Inner loop identical to R14. Outputs 5 partial stats per row to g_stats.
// ---------------------------------------------------------------------------
__global__ __launch_bounds__(256,2)
void loss_kernel(const float* __restrict__ wts)
{
    extern __shared__ __align__(16) char smem[];
    const uint32_t sb = (uint32_t)__cvta_generic_to_shared(smem);
    const int item  = blockIdx.x;
    const int chunk = item & (NCHUNK-1);
    const int it    = (item >> 3) & (NIT-1);
    const int b     = item >> 9;
    const int i0  = it*BM;
    const int jt0 = chunk*TPC, jtEnd = jt0 + TPC;
    const int tid = threadIdx.x;
    const int w = tid>>5, lane = tid&31;
    const int wm = w&3, wn = w>>2;
    const int g = lane>>2, tig = lane&3;

    // prologue: A + B(jt0) + P(jt0) (group0), B(jt0+1) + P (group1)
    {
        const char* gA = (const char*)(g_pk1 + (size_t)(b*NPTS+i0)*64);
        #pragma unroll
        for(int q=0;q<4;q++){
            int idx=q*256+tid, r=idx>>4, c=idx&15;
            cpa16(sb + OFF_A + r*ROWB + c*16, gA + r*256 + c*16);
        }
        load_B_tile(sb, tid, b, jt0);
        asm volatile("cp.async.commit_group;\n");
        load_B_tile(sb, tid, b, jt0+1);
        asm volatile("cp.async.commit_group;\n");
    }

    const uint32_t aAddr = sb + OFF_A + (wm*16 + (lane&15))*ROWB + (lane>>4)*16;
    const int bn_row = (lane&7) + (((lane>>4)&1)<<3);
    const uint32_t bk16 = ((lane>>3)&1)*16;

    uint64_t x2xp, x2yp, x2zp, nnip;
    {
        int rl0 = wm*16 + g, rl1 = rl0 + 8;
        float4 v0 = g_pi[b*NPTS + i0 + rl0];
        float4 v1 = g_pi[b*NPTS + i0 + rl1];
        x2xp = pk2(v0.x+v0.x, v1.x+v1.x);
        x2yp = pk2(v0.y+v0.y, v1.y+v1.y);
        x2zp = pk2(v0.z+v0.z, v1.z+v1.z);
        nnip = pk2(-fmaf(v0.x,v0.x, fmaf(v0.y,v0.y, v0.z*v0.z)),
                   -fmaf(v1.x,v1.x, fmaf(v1.y,v1.y, v1.z*v1.z)));
    }
    uint64_t Z1p = pk2(0.f,0.f), Z2p = Z1p, Avp = Z1p, Bvp = Z1p, Cvp = Z1p;

    asm volatile("cp.async.wait_group 1;\n" ::: "memory");
    __syncthreads();

    uint32_t ah[4][4], al[4][4];
    #pragma unroll
    for(int c=0;c<4;c++){
        ldmx4(ah[c][0],ah[c][1],ah[c][2],ah[c][3], aAddr + c*32);
        ldmx4(al[c][0],al[c][1],al[c][2],al[c][3], aAddr + 128 + c*32);
    }

    for(int jt=jt0; jt<jtEnd; jt++){
        const int buf = jt&1;
        float acc[4][4];
        #pragma unroll
        for(int nb=0;nb<4;nb++)
            #pragma unroll
            for(int q=0;q<4;q++) acc[nb][q]=0.f;
        #pragma unroll
        for(int c=0;c<4;c++){
            #pragma unroll
            for(int n2=0;n2<2;n2++){
                uint32_t ba = sb + OFF_B + buf*SZ_B
                            + (wn*32 + n2*16 + bn_row)*ROWB + bk16;
                uint32_t bh[4], bl[4];
                ldmx4(bh[0],bh[1],bh[2],bh[3], ba + c*32);
                ldmx4(bl[0],bl[1],bl[2],bl[3], ba + 128 + c*32);
                mma16816(acc[n2*2+0], ah[c], bh[0], bh[1]);
                mma16816(acc[n2*2+1], ah[c], bh[2], bh[3]);
                mma16816(acc[n2*2+0], ah[c], bl[0], bl[1]);
                mma16816(acc[n2*2+1], ah[c], bl[2], bl[3]);
                mma16816(acc[n2*2+0], al[c], bh[0], bh[1]);
                mma16816(acc[n2*2+1], al[c], bh[2], bh[3]);
            }
        }

        if (jt+1 < jtEnd){
            asm volatile("cp.async.wait_group 0;\n" ::: "memory");
        }
        __syncthreads();
        if (jt+2 < jtEnd){
            load_B_tile(sb, tid, b, jt+2);
            asm volatile("cp.async.commit_group;\n");
        }

        {
            const float4* pP = (const float4*)(smem + OFF_P + (jt&3)*SZ_P);
            const float*  pC = (const float*) (smem + OFF_P + (jt&3)*SZ_P + 1024);
            #pragma unroll
            for(int nb=0;nb<4;nb++){
                #pragma unroll
                for(int q=0;q<2;q++){
                    int c = wn*32 + nb*8 + tig*2 + q;
                    float4 v = pP[c];
                    float cn = pC[c];                       // already negated
                    uint64_t ttp = fma2(x2xp, pk2(v.x,v.x),
                                   fma2(x2yp, pk2(v.y,v.y),
                                   fma2(x2zp, pk2(v.z,v.z),
                                   add2(pk2(v.w,v.w), nnip))));
                    uint64_t s2p = add2(pk2(acc[nb][q], acc[nb][2+q]),
                                        pk2(cn, cn));
                    float t0,t1, sa,sb2;
                    upk2(ttp, t0, t1);
                    upk2(s2p, sa, sb2);
                    float e1a = ex2(t0), e1b = ex2(t1);
                    float e2a = ex2(sa), e2b = ex2(sb2);
                    uint64_t e1p = pk2(e1a, e1b);
                    uint64_t e2p = pk2(e2a, e2b);
                    Z1p = add2(Z1p, e1p);
                    Avp = fma2(e1p, e1p, Avp);
                    Z2p = add2(Z2p, e2p);
                    Bvp = fma2(e2p, e2p, Bvp);
                    Cvp = fma2(e1p, e2p, Cvp);
                }
            }
        }
    }

    float Z1[2],Z2[2],Av[2],Bv[2],Cv[2];
    upk2(Z1p, Z1[0], Z1[1]);
    upk2(Z2p, Z2[0], Z2[1]);
    upk2(Avp, Av[0], Av[1]);
    upk2(Bvp, Bv[0], Bv[1]);
    upk2(Cvp, Cv[0], Cv[1]);

    // merge 4 tig-lanes per row
    #pragma unroll
    for(int h=0;h<2;h++){
        #pragma unroll
        for(int off=1; off<=2; off<<=1){
            Z1[h] += __shfl_xor_sync(~0u, Z1[h], off);
            Z2[h] += __shfl_xor_sync(~0u, Z2[h], off);
            Av[h] += __shfl_xor_sync(~0u, Av[h], off);
            Bv[h] += __shfl_xor_sync(~0u, Bv[h], off);
            Cv[h] += __shfl_xor_sync(~0u, Cv[h], off);
        }
    }
    // merge the two wn col-bands via smem, then store partial stats to gmem
    float* sM = (float*)(smem + OFF_M);
    if (wn==1 && tig==0){
        #pragma unroll
        for(int h=0;h<2;h++){
            int rl = wm*16 + g + h*8;
            float* p = sM + rl*5;
            p[0]=Z1[h]; p[1]=Z2[h]; p[2]=Av[h]; p[3]=Bv[h]; p[4]=Cv[h];
        }
    }
    __syncthreads();
    if (wn==0 && tig==0){
        float* gs = g_stats + (size_t)item*320;
        #pragma unroll
        for(int h=0;h<2;h++){
            int rl = wm*16 + g + h*8;
            const float* p = sM + rl*5;
            gs[0*64+rl] = Z1[h] + p[0];
            gs[1*64+rl] = Z2[h] + p[1];
            gs[2*64+rl] = Av[h] + p[2];
            gs[3*64+rl] = Bv[h] + p[3];
            gs[4*64+rl] = Cv[h] + p[4];
        }
    }
}

// ---------------------------------------------------------------------------
// merge: per (it,b) sum the 8 chunk partials per row, compute weighted loss.
// ---------------------------------------------------------------------------
__global__ void merge_kernel(const float* __restrict__ wts)
{
    const int it = blockIdx.x, b = blockIdx.y;
    const int r  = threadIdx.x;            // 64 threads, one row each
    const float* base = g_stats + (size_t)((b*NIT + it)*NCHUNK)*320;
    float Z1=0.f,Z2=0.f,Av=0.f,Bv=0.f,Cv=0.f;
    #pragma unroll
    for(int c=0;c<NCHUNK;c++){
        const float* p = base + c*320;
        Z1 += p[0*64+r]; Z2 += p[1*64+r]; Av += p[2*64+r];
        Bv += p[3*64+r]; Cv += p[4*64+r];
    }
    float i1 = 1.0f/Z1, i2 = 1.0f/Z2;
    float loss = Av*i1*i1 - 2.0f*((Cv*i2)*i1) + (Bv*i2)*i2;
    float wacc = wts[b*NPTS + it*BM + r] * loss;
    // block reduce (64 threads = 2 warps)
    #pragma unroll
    for(int off=16; off>=1; off>>=1) wacc += __shfl_xor_sync(~0u, wacc, off);
    __shared__ float ss[2];
    if ((r&31)==0) ss[r>>5] = wacc;
    __syncthreads();
    if (r==0) g_partial[b*NIT + it] = ss[0] + ss[1];
}

// ---------------------------------------------------------------------------
__global__ void reduce_kernel(float* __restrict__ out)
{
    int b    = threadIdx.x >> 5;
    int lane = threadIdx.x & 31;
    float s = g_partial[b*NIT + lane] + g_partial[b*NIT + 32 + lane];
    #pragma unroll
    for(int off=16; off>=1; off>>=1) s += __shfl_xor_sync(~0u, s, off);
    if (lane==0) out[b] = s;
}

// ---------------------------------------------------------------------------
extern "C" void kernel_launch(void* const* d_in, const int* in_sizes, int n_in,
                              void* d_out, int out_size)
{
    const float* pts = (const float*)d_in[0];
    const float* wts = (const float*)d_in[1];
    const float* f1  = (const float*)d_in[2];
    const float* f2  = (const float*)d_in[3];
    float* out = (float*)d_out;

    cudaFuncSetAttribute(loss_kernel, cudaFuncAttributeMaxDynamicSharedMemorySize, SMEM_TOTAL);
    prep_kernel<<<(BATCH*NPTS + 255)/256, 256>>>(pts, f1, f2);
    loss_kernel<<<BATCH*NIT*NCHUNK, 256, SMEM_TOTAL>>>(wts);
    dim3 mgrid(NIT, BATCH);
    merge_kernel<<<mgrid, 64>>>(wts);
    reduce_kernel<<<1, 128>>>(out);
}